// round 14
// baseline (speedup 1.0000x reference)
#include <cuda_runtime.h>
#include <cuda_fp16.h>
#include <cstdint>
#include <cstddef>

#define N_NODES 100000
#define N_EDGES 600000
#define D_IN 128
#define D_OUT 512
#define BM 64
#define MT_TOTAL 1563                // ceil(100000/64)
#define M_PAD (MT_TOTAL * BM)        // 100032

// ---------------- device scratch (static; no runtime allocs) ----------------
__device__ float g_agg[(size_t)N_NODES * D_IN];             // 51.2 MB
__device__ __half g_Ah[(size_t)M_PAD * D_IN];               // 25.6 MB
__device__ __half g_Al[(size_t)M_PAD * D_IN];               // 25.6 MB
__device__ __half g_Wh[D_OUT * D_IN];
__device__ int g_is64;

// ---------------- fused setup: detect dtype + W->fp16 + agg=x ----------------
#define CONV_BLOCKS 256                        // 65536 / 256
#define COPY_CHUNKS (N_NODES * D_IN / 4)       // 3.2M float4
#define COPY_BLOCKS ((COPY_CHUNKS + 255) / 256)
__global__ void setup_kernel(const int* __restrict__ ei_w,
                             const float* __restrict__ W,
                             const float* __restrict__ x) {
    int b = blockIdx.x;
    if (b == 0) {
        int any = 0;
        for (int i = threadIdx.x; i < 1024; i += 256)
            if (ei_w[2 * i + 1] != 0) any = 1;
        any = __syncthreads_or(any);
        if (threadIdx.x == 0) g_is64 = !any;
    } else if (b <= CONV_BLOCKS) {
        int i = (b - 1) * 256 + threadIdx.x;
        g_Wh[i] = __float2half_rn(W[i]);
    } else {
        int i = (b - 1 - CONV_BLOCKS) * 256 + threadIdx.x;
        if (i < COPY_CHUNKS)
            reinterpret_cast<float4*>(g_agg)[i] = reinterpret_cast<const float4*>(x)[i];
    }
}

// ---------------- scatter: one warp per 8 edges (MLP=8) ----------------
#define EDGES_PER_WARP 8
__global__ void scatter_kernel(const void* __restrict__ ei, const float* __restrict__ x) {
    int w = (blockIdx.x * blockDim.x + threadIdx.x) >> 5;
    int e0 = w * EDGES_PER_WARP;
    if (e0 >= N_EDGES) return;
    int lane = threadIdx.x & 31;

    int dst[EDGES_PER_WARP], src[EDGES_PER_WARP];
    if (g_is64) {
        const long long* e = reinterpret_cast<const long long*>(ei);
        #pragma unroll
        for (int j = 0; j < EDGES_PER_WARP; j++) {
            dst[j] = (int)__ldg(e + e0 + j);
            src[j] = (int)__ldg(e + N_EDGES + e0 + j);
        }
    } else {
        const int* e = reinterpret_cast<const int*>(ei);
        #pragma unroll
        for (int j = 0; j < EDGES_PER_WARP; j++) {
            dst[j] = __ldg(e + e0 + j);
            src[j] = __ldg(e + N_EDGES + e0 + j);
        }
    }
    float4 v[EDGES_PER_WARP];
    #pragma unroll
    for (int j = 0; j < EDGES_PER_WARP; j++)
        v[j] = reinterpret_cast<const float4*>(x + (size_t)src[j] * D_IN)[lane];
    #pragma unroll
    for (int j = 0; j < EDGES_PER_WARP; j++) {
        float* p = g_agg + (size_t)dst[j] * D_IN + lane * 4;
        asm volatile("red.global.add.v4.f32 [%0], {%1, %2, %3, %4};"
                     :: "l"(p), "f"(v[j].x), "f"(v[j].y), "f"(v[j].z), "f"(v[j].w)
                     : "memory");
    }
}

// ---------------- agg fp32 -> fp16 hi/lo (zero-padded to M_PAD rows) ----------------
__global__ void split_kernel() {
    size_t t = (size_t)blockIdx.x * blockDim.x + threadIdx.x;
    size_t i = t * 8;                       // float index
    if (i >= (size_t)M_PAD * D_IN) return;
    size_t row = i >> 7;
    float f[8];
    if (row < N_NODES) {
        float4 v0 = *reinterpret_cast<const float4*>(g_agg + i);
        float4 v1 = *reinterpret_cast<const float4*>(g_agg + i + 4);
        f[0] = v0.x; f[1] = v0.y; f[2] = v0.z; f[3] = v0.w;
        f[4] = v1.x; f[5] = v1.y; f[6] = v1.z; f[7] = v1.w;
    } else {
        #pragma unroll
        for (int j = 0; j < 8; j++) f[j] = 0.f;
    }
    __half h[8], l[8];
    #pragma unroll
    for (int j = 0; j < 8; j++) {
        h[j] = __float2half_rn(f[j]);
        l[j] = __float2half_rn(f[j] - __half2float(h[j]));
    }
    *reinterpret_cast<uint4*>(g_Ah + i) = *reinterpret_cast<uint4*>(h);
    *reinterpret_cast<uint4*>(g_Al + i) = *reinterpret_cast<uint4*>(l);
}

// ---------------- GEMM helpers ----------------
__device__ __forceinline__ uint32_t smem_u32(const void* p) {
    return (uint32_t)__cvta_generic_to_shared(p);
}
__device__ __forceinline__ void ldsm_x4(uint32_t* r, uint32_t addr) {
    asm volatile("ldmatrix.sync.aligned.m8n8.x4.shared.b16 {%0,%1,%2,%3}, [%4];"
                 : "=r"(r[0]), "=r"(r[1]), "=r"(r[2]), "=r"(r[3]) : "r"(addr));
}
__device__ __forceinline__ void mma_fp16(float* c, const uint32_t* a, const uint32_t* b) {
    asm volatile("mma.sync.aligned.m16n8k16.row.col.f32.f16.f16.f32 "
                 "{%0,%1,%2,%3}, {%4,%5,%6,%7}, {%8,%9}, {%0,%1,%2,%3};"
                 : "+f"(c[0]), "+f"(c[1]), "+f"(c[2]), "+f"(c[3])
                 : "r"(a[0]), "r"(a[1]), "r"(a[2]), "r"(a[3]),
                   "r"(b[0]), "r"(b[1]));
}
__device__ __forceinline__ void cp16(uint32_t dst, const void* src) {
    asm volatile("cp.async.cg.shared.global [%0], [%1], 16;" :: "r"(dst), "l"(src));
}

// smem layout (bytes): B(Wh,128x128) + 2 x A-pair(64x128 hi+lo) = 102 KB -> 2 CTAs/SM
#define LDSTRIDE 136                       // fp16 elems per row (272 B)
#define B_BYTES (128 * LDSTRIDE * 2)       // 34816
#define A_HALF  (BM * LDSTRIDE * 2)        // 17408 (one of Ah/Al)
#define A_PAIR  (2 * A_HALF)               // 34816
#define SM_B  0
#define SM_A  B_BYTES
#define SM_TOTAL (B_BYTES + 2 * A_PAIR)    // 104448

#define GEMM_THREADS 256
#define M_CTAS 74                          // x4 n-cols = 296 CTAs = 2/SM

__device__ __forceinline__ void prefetch_tile(int mt, uint32_t aH, uint32_t aL, int tid) {
    const char* sH = (const char*)(g_Ah + (size_t)mt * BM * D_IN);
    const char* sL = (const char*)(g_Al + (size_t)mt * BM * D_IN);
    #pragma unroll
    for (int i = 0; i < 4; i++) {
        int lin = tid + GEMM_THREADS * i;  // 0..1023
        int r = lin >> 4;                  // row 0..63
        int c = (lin & 15) << 4;           // byte col 0..240
        cp16(aH + r * 272 + c, sH + r * 256 + c);
        cp16(aL + r * 272 + c, sL + r * 256 + c);
    }
    asm volatile("cp.async.commit_group;" ::: "memory");
}

// ---------------- persistent 2-CTA/SM double-buffered merged-pass fp16 GEMM ----------------
__global__ __launch_bounds__(GEMM_THREADS, 2) void gemm_kernel(const float* __restrict__ bias,
                                                               float* __restrict__ out) {
    extern __shared__ char smem[];
    const uint32_t sb = smem_u32(smem);
    const int tid = threadIdx.x, wid = tid >> 5, lane = tid & 31;
    const int n0 = blockIdx.y * 128;

    __half* BH = reinterpret_cast<__half*>(smem + SM_B);

    // ---- load Wh tile once (resident for all m-tiles) ----
    {
        const __half* WH = g_Wh + (size_t)n0 * D_IN;
        #pragma unroll
        for (int i = 0; i < 8; i++) {
            int lin = i * GEMM_THREADS + tid; // 0..2047 uint4s
            int r = lin >> 4;                 // n-row
            int u = (lin & 15) << 3;          // fp16 col
            *reinterpret_cast<uint4*>(BH + r * LDSTRIDE + u) =
                *reinterpret_cast<const uint4*>(WH + (size_t)r * D_IN + u);
        }
    }

    // 8 warps: 2(m) x 4(n); warp tile 32x32
    const int wm = (wid & 1) << 5;
    const int wn = (wid >> 1) << 5;
    const int a_r  = lane & 15;
    const int a_k8 = (lane >> 4) << 3;
    const int b_r  = ((lane >> 4) << 3) + (lane & 7);
    const int b_k8 = ((lane >> 3) & 1) << 3;
    const int gr = lane >> 2;
    const int gc = (lane & 3) << 1;

    // ---- prologue prefetch ----
    int mt = blockIdx.x;
    prefetch_tile(mt, sb + SM_A, sb + SM_A + A_HALF, tid);

    int buf = 0;
    for (; mt < MT_TOTAL; mt += M_CTAS, buf ^= 1) {
        asm volatile("cp.async.wait_group 0;" ::: "memory");
        __syncthreads();   // A[buf] visible; all warps done with A[buf^1]

        int nmt = mt + M_CTAS;
        if (nmt < MT_TOTAL) {
            uint32_t nb = sb + SM_A + (uint32_t)(buf ^ 1) * A_PAIR;
            prefetch_tile(nmt, nb, nb + A_HALF, tid);
        }

        __half* AH = reinterpret_cast<__half*>(smem + SM_A + buf * A_PAIR);
        __half* AL = AH + BM * LDSTRIDE;

        float acc[2][4][4];
        #pragma unroll
        for (int i = 0; i < 2; i++)
            #pragma unroll
            for (int j = 0; j < 4; j++)
                #pragma unroll
                for (int q = 0; q < 4; q++) acc[i][j][q] = 0.f;

        // ---- merged hi/lo passes: each B fragment loaded ONCE per k-step ----
        #pragma unroll
        for (int k = 0; k < D_IN; k += 16) {
            uint32_t ah[2][4], al[2][4];
            #pragma unroll
            for (int mf = 0; mf < 2; mf++) {
                ldsm_x4(ah[mf], smem_u32(AH + (wm + mf * 16 + a_r) * LDSTRIDE + k + a_k8));
                ldsm_x4(al[mf], smem_u32(AL + (wm + mf * 16 + a_r) * LDSTRIDE + k + a_k8));
            }
            #pragma unroll
            for (int nf2 = 0; nf2 < 2; nf2++) {
                uint32_t b4[4];
                ldsm_x4(b4, smem_u32(BH + (wn + nf2 * 16 + b_r) * LDSTRIDE + k + b_k8));
                #pragma unroll
                for (int mf = 0; mf < 2; mf++) {
                    mma_fp16(acc[mf][nf2 * 2],     ah[mf], b4);
                    mma_fp16(acc[mf][nf2 * 2 + 1], ah[mf], b4 + 2);
                    mma_fp16(acc[mf][nf2 * 2],     al[mf], b4);
                    mma_fp16(acc[mf][nf2 * 2 + 1], al[mf], b4 + 2);
                }
            }
        }

        // ---- epilogue: + bias, fp32 stores (no trailing sync: warps may skew) ----
        const int m0 = mt * BM;
        #pragma unroll
        for (int mf = 0; mf < 2; mf++) {
            #pragma unroll
            for (int nf = 0; nf < 4; nf++) {
                int col = n0 + wn + nf * 8 + gc;
                float2 bv = *reinterpret_cast<const float2*>(bias + col);
                int row0 = m0 + wm + mf * 16 + gr;
                if (row0 < N_NODES) {
                    float2 o = make_float2(acc[mf][nf][0] + bv.x, acc[mf][nf][1] + bv.y);
                    *reinterpret_cast<float2*>(out + (size_t)row0 * D_OUT + col) = o;
                }
                int row1 = row0 + 8;
                if (row1 < N_NODES) {
                    float2 o = make_float2(acc[mf][nf][2] + bv.x, acc[mf][nf][3] + bv.y);
                    *reinterpret_cast<float2*>(out + (size_t)row1 * D_OUT + col) = o;
                }
            }
        }
    }
}

extern "C" void kernel_launch(void* const* d_in, const int* in_sizes, int n_in,
                              void* d_out, int out_size) {
    const float* x  = (const float*)d_in[0];
    const void*  ei = d_in[1];            // int64 or int32 — detected on device
    const float* W  = (const float*)d_in[2];
    const float* b  = (const float*)d_in[3];
    float* out = (float*)d_out;

    cudaFuncSetAttribute(gemm_kernel, cudaFuncAttributeMaxDynamicSharedMemorySize, SM_TOTAL);

    setup_kernel<<<1 + CONV_BLOCKS + COPY_BLOCKS, 256>>>((const int*)ei, W, x);

    int n_warps = N_EDGES / EDGES_PER_WARP;               // 75000
    scatter_kernel<<<(n_warps + 7) / 8, 256>>>(ei, x);

    size_t split_threads = (size_t)M_PAD * D_IN / 8;
    split_kernel<<<(unsigned)((split_threads + 255) / 256), 256>>>();

    dim3 grid(M_CTAS, 4);
    gemm_kernel<<<grid, GEMM_THREADS, SM_TOTAL>>>(b, out);
}

// round 17
// speedup vs baseline: 1.6200x; 1.6200x over previous
#include <cuda_runtime.h>
#include <cuda_fp16.h>
#include <cstdint>
#include <cstddef>

#define N_NODES 100000
#define N_EDGES 600000
#define D_IN 128
#define D_OUT 512
#define BM 64
#define MT_TOTAL 1563                // ceil(100000/64)
#define M_PAD (MT_TOTAL * BM)        // 100032

// ---------------- device scratch (static; no runtime allocs) ----------------
// g_aggh rows [N_NODES, M_PAD) are never written -> stay zero from static init.
__device__ __half g_xh[(size_t)N_NODES * D_IN];             // fp16 copy of x (gather src)
__device__ __half g_aggh[(size_t)M_PAD * D_IN];             // fp16 accumulator / GEMM A
__device__ __half g_Wh[D_OUT * D_IN];
__device__ int g_is64;

// ---------------- fused setup: detect dtype + W->fp16 + x->fp16 (xh & aggh) ----------------
#define CONV_BLOCKS 256                        // 65536 / 256
#define XCHUNKS (N_NODES * D_IN / 8)           // 1.6M chunks of 8 floats
#define XBLOCKS ((XCHUNKS + 255) / 256)        // 6250
__global__ void setup_kernel(const int* __restrict__ ei_w,
                             const float* __restrict__ W,
                             const float* __restrict__ x) {
    int b = blockIdx.x;
    if (b == 0) {
        int any = 0;
        for (int i = threadIdx.x; i < 1024; i += 256)
            if (ei_w[2 * i + 1] != 0) any = 1;
        any = __syncthreads_or(any);
        if (threadIdx.x == 0) g_is64 = !any;
    } else if (b <= CONV_BLOCKS) {
        int i = (b - 1) * 256 + threadIdx.x;
        g_Wh[i] = __float2half_rn(W[i]);
    } else {
        size_t t = (size_t)(b - 1 - CONV_BLOCKS) * 256 + threadIdx.x;
        if (t < XCHUNKS) {
            size_t i = t * 8;
            float4 v0 = *reinterpret_cast<const float4*>(x + i);
            float4 v1 = *reinterpret_cast<const float4*>(x + i + 4);
            __half h[8];
            h[0] = __float2half_rn(v0.x); h[1] = __float2half_rn(v0.y);
            h[2] = __float2half_rn(v0.z); h[3] = __float2half_rn(v0.w);
            h[4] = __float2half_rn(v1.x); h[5] = __float2half_rn(v1.y);
            h[6] = __float2half_rn(v1.z); h[7] = __float2half_rn(v1.w);
            uint4 packed = *reinterpret_cast<uint4*>(h);
            *reinterpret_cast<uint4*>(g_xh + i)   = packed;
            *reinterpret_cast<uint4*>(g_aggh + i) = packed;   // residual init
        }
    }
}

// ---------------- scatter: fp16 gather + red.global.add.v4.f16x2 ----------------
// Two edges per warp-pass: lanes 0-15 -> edge j, lanes 16-31 -> edge j+1.
// 16 B per lane covers 8 halves; 16 lanes cover a 128-half row.
#define EDGES_PER_WARP 8
__global__ void scatter_kernel(const void* __restrict__ ei) {
    int w = (blockIdx.x * blockDim.x + threadIdx.x) >> 5;
    int e0 = w * EDGES_PER_WARP;
    if (e0 >= N_EDGES) return;
    int lane = threadIdx.x & 31;
    int half = lane >> 4;               // 0/1: which edge of the pair
    int sub  = lane & 15;               // 16-byte slot within the row

    int dst[4], src[4];
    if (g_is64) {
        const long long* e = reinterpret_cast<const long long*>(ei);
        #pragma unroll
        for (int j = 0; j < 4; j++) {
            int idx = e0 + 2 * j + half;
            dst[j] = (int)__ldg(e + idx);
            src[j] = (int)__ldg(e + N_EDGES + idx);
        }
    } else {
        const int* e = reinterpret_cast<const int*>(ei);
        #pragma unroll
        for (int j = 0; j < 4; j++) {
            int idx = e0 + 2 * j + half;
            dst[j] = __ldg(e + idx);
            src[j] = __ldg(e + N_EDGES + idx);
        }
    }
    uint4 v[4];
    #pragma unroll
    for (int j = 0; j < 4; j++)
        v[j] = *reinterpret_cast<const uint4*>(g_xh + (size_t)src[j] * D_IN + sub * 8);
    #pragma unroll
    for (int j = 0; j < 4; j++) {
        __half* p = g_aggh + (size_t)dst[j] * D_IN + sub * 8;
        asm volatile("red.global.add.noftz.v4.f16x2 [%0], {%1, %2, %3, %4};"
                     :: "l"(p), "r"(v[j].x), "r"(v[j].y), "r"(v[j].z), "r"(v[j].w)
                     : "memory");
    }
}

// ---------------- GEMM helpers ----------------
__device__ __forceinline__ uint32_t smem_u32(const void* p) {
    return (uint32_t)__cvta_generic_to_shared(p);
}
__device__ __forceinline__ void ldsm_x4(uint32_t* r, uint32_t addr) {
    asm volatile("ldmatrix.sync.aligned.m8n8.x4.shared.b16 {%0,%1,%2,%3}, [%4];"
                 : "=r"(r[0]), "=r"(r[1]), "=r"(r[2]), "=r"(r[3]) : "r"(addr));
}
__device__ __forceinline__ void mma_fp16(float* c, const uint32_t* a, const uint32_t* b) {
    asm volatile("mma.sync.aligned.m16n8k16.row.col.f32.f16.f16.f32 "
                 "{%0,%1,%2,%3}, {%4,%5,%6,%7}, {%8,%9}, {%0,%1,%2,%3};"
                 : "+f"(c[0]), "+f"(c[1]), "+f"(c[2]), "+f"(c[3])
                 : "r"(a[0]), "r"(a[1]), "r"(a[2]), "r"(a[3]),
                   "r"(b[0]), "r"(b[1]));
}
__device__ __forceinline__ void cp16(uint32_t dst, const void* src) {
    asm volatile("cp.async.cg.shared.global [%0], [%1], 16;" :: "r"(dst), "l"(src));
}

// smem layout (bytes): B(Wh,128x128) + 2 x A(64x128) = 68 KB -> 2 CTAs/SM easily
#define LDSTRIDE 136                       // fp16 elems per row (272 B)
#define B_BYTES (128 * LDSTRIDE * 2)       // 34816
#define A_TILE  (BM * LDSTRIDE * 2)        // 17408
#define SM_B  0
#define SM_A  B_BYTES
#define SM_TOTAL (B_BYTES + 2 * A_TILE)    // 69632

#define GEMM_THREADS 256
#define M_CTAS 74                          // x4 n-cols = 296 CTAs = 2/SM

__device__ __forceinline__ void prefetch_tile(int mt, uint32_t aDst, int tid) {
    const char* sA = (const char*)(g_aggh + (size_t)mt * BM * D_IN);
    #pragma unroll
    for (int i = 0; i < 4; i++) {
        int lin = tid + GEMM_THREADS * i;  // 0..1023
        int r = lin >> 4;                  // row 0..63
        int c = (lin & 15) << 4;           // byte col 0..240
        cp16(aDst + r * 272 + c, sA + r * 256 + c);
    }
    asm volatile("cp.async.commit_group;" ::: "memory");
}

// ---------------- persistent 2-CTA/SM double-buffered single-pass fp16 GEMM ----------------
__global__ __launch_bounds__(GEMM_THREADS, 2) void gemm_kernel(const float* __restrict__ bias,
                                                               float* __restrict__ out) {
    extern __shared__ char smem[];
    const uint32_t sb = smem_u32(smem);
    const int tid = threadIdx.x, wid = tid >> 5, lane = tid & 31;
    const int n0 = blockIdx.y * 128;

    __half* BH = reinterpret_cast<__half*>(smem + SM_B);

    // ---- load Wh tile once (resident for all m-tiles) ----
    {
        const __half* WH = g_Wh + (size_t)n0 * D_IN;
        #pragma unroll
        for (int i = 0; i < 8; i++) {
            int lin = i * GEMM_THREADS + tid; // 0..2047 uint4s
            int r = lin >> 4;                 // n-row
            int u = (lin & 15) << 3;          // fp16 col
            *reinterpret_cast<uint4*>(BH + r * LDSTRIDE + u) =
                *reinterpret_cast<const uint4*>(WH + (size_t)r * D_IN + u);
        }
    }

    // 8 warps: 2(m) x 4(n); warp tile 32x32
    const int wm = (wid & 1) << 5;
    const int wn = (wid >> 1) << 5;
    const int a_r  = lane & 15;
    const int a_k8 = (lane >> 4) << 3;
    const int b_r  = ((lane >> 4) << 3) + (lane & 7);
    const int b_k8 = ((lane >> 3) & 1) << 3;
    const int gr = lane >> 2;
    const int gc = (lane & 3) << 1;

    // ---- prologue prefetch ----
    int mt = blockIdx.x;
    prefetch_tile(mt, sb + SM_A, tid);

    int buf = 0;
    for (; mt < MT_TOTAL; mt += M_CTAS, buf ^= 1) {
        asm volatile("cp.async.wait_group 0;" ::: "memory");
        __syncthreads();   // A[buf] visible; all warps done with A[buf^1]

        int nmt = mt + M_CTAS;
        if (nmt < MT_TOTAL)
            prefetch_tile(nmt, sb + SM_A + (uint32_t)(buf ^ 1) * A_TILE, tid);

        __half* AH = reinterpret_cast<__half*>(smem + SM_A + buf * A_TILE);

        float acc[2][4][4];
        #pragma unroll
        for (int i = 0; i < 2; i++)
            #pragma unroll
            for (int j = 0; j < 4; j++)
                #pragma unroll
                for (int q = 0; q < 4; q++) acc[i][j][q] = 0.f;

        #pragma unroll
        for (int k = 0; k < D_IN; k += 16) {
            uint32_t ah[2][4];
            #pragma unroll
            for (int mf = 0; mf < 2; mf++)
                ldsm_x4(ah[mf], smem_u32(AH + (wm + mf * 16 + a_r) * LDSTRIDE + k + a_k8));
            #pragma unroll
            for (int nf2 = 0; nf2 < 2; nf2++) {
                uint32_t b4[4];
                ldsm_x4(b4, smem_u32(BH + (wn + nf2 * 16 + b_r) * LDSTRIDE + k + b_k8));
                #pragma unroll
                for (int mf = 0; mf < 2; mf++) {
                    mma_fp16(acc[mf][nf2 * 2],     ah[mf], b4);
                    mma_fp16(acc[mf][nf2 * 2 + 1], ah[mf], b4 + 2);
                }
            }
        }

        // ---- epilogue: + bias, fp32 stores (no trailing sync: warps may skew) ----
        const int m0 = mt * BM;
        #pragma unroll
        for (int mf = 0; mf < 2; mf++) {
            #pragma unroll
            for (int nf = 0; nf < 4; nf++) {
                int col = n0 + wn + nf * 8 + gc;
                float2 bv = *reinterpret_cast<const float2*>(bias + col);
                int row0 = m0 + wm + mf * 16 + gr;
                if (row0 < N_NODES) {
                    float2 o = make_float2(acc[mf][nf][0] + bv.x, acc[mf][nf][1] + bv.y);
                    *reinterpret_cast<float2*>(out + (size_t)row0 * D_OUT + col) = o;
                }
                int row1 = row0 + 8;
                if (row1 < N_NODES) {
                    float2 o = make_float2(acc[mf][nf][2] + bv.x, acc[mf][nf][3] + bv.y);
                    *reinterpret_cast<float2*>(out + (size_t)row1 * D_OUT + col) = o;
                }
            }
        }
    }
}

extern "C" void kernel_launch(void* const* d_in, const int* in_sizes, int n_in,
                              void* d_out, int out_size) {
    const void*  ei = d_in[1];            // int64 or int32 — detected on device
    const float* W  = (const float*)d_in[2];
    const float* b  = (const float*)d_in[3];
    const float* x  = (const float*)d_in[0];
    float* out = (float*)d_out;

    cudaFuncSetAttribute(gemm_kernel, cudaFuncAttributeMaxDynamicSharedMemorySize, SM_TOTAL);

    setup_kernel<<<1 + CONV_BLOCKS + XBLOCKS, 256>>>((const int*)ei, W, x);

    int n_warps = N_EDGES / EDGES_PER_WARP;               // 75000
    scatter_kernel<<<(n_warps + 7) / 8, 256>>>(ei);

    dim3 grid(M_CTAS, 4);
    gemm_kernel<<<grid, GEMM_THREADS, SM_TOTAL>>>(b, out);
}